// round 3
// baseline (speedup 1.0000x reference)
#include <cuda_runtime.h>
#include <math.h>

#define HH    512
#define NIMG  72          // B(8) * M(3) * W(3); wavelength = img % 3
#define NWL   3
#define NLAY  5
#define LBUF  576         // 512 + 512/8 padding
#define PADI(i) ((i) + ((i) >> 3))

// -------- precomputed tables (__device__ globals = sanctioned scratch) --------
__device__ float2 d_HL[NWL * HH * HH];               // exp(i kz zL) / 512
__device__ float2 d_HD[NWL * HH * HH];               // exp(i kz zD) / 512  (one F_r pair cancelled)
__device__ float2 d_expP[NLAY * NWL * HH * HH];      // exp(i phase) (layers>0 scaled 1/512)

__device__ __forceinline__ float2 cmulf(float2 a, float2 b) {
    return make_float2(a.x * b.x - a.y * b.y, a.x * b.y + a.y * b.x);
}

template <int SGN>
__device__ __forceinline__ float2 muli(float2 z) {   // SGN * i * z
    return (SGN > 0) ? make_float2(-z.y, z.x) : make_float2(z.y, -z.x);
}

// natural-order 8-point DFT: b_k = sum_j a_j * e^{SGN*2*pi*i*j*k/8}
template <int SGN>
__device__ __forceinline__ void dft8(float2 v[8]) {
    const float C = 0.70710678118654752f;
    const float sg = (float)SGN;
    float2 t0 = make_float2(v[0].x + v[4].x, v[0].y + v[4].y);
    float2 t1 = make_float2(v[0].x - v[4].x, v[0].y - v[4].y);
    float2 t2 = make_float2(v[2].x + v[6].x, v[2].y + v[6].y);
    float2 t3 = make_float2(v[2].x - v[6].x, v[2].y - v[6].y);
    float2 u0 = make_float2(v[1].x + v[5].x, v[1].y + v[5].y);
    float2 u1 = make_float2(v[1].x - v[5].x, v[1].y - v[5].y);
    float2 u2 = make_float2(v[3].x + v[7].x, v[3].y + v[7].y);
    float2 u3 = make_float2(v[3].x - v[7].x, v[3].y - v[7].y);
    float2 it3 = muli<SGN>(t3);
    float2 iu3 = muli<SGN>(u3);
    float2 E0 = make_float2(t0.x + t2.x, t0.y + t2.y);
    float2 E2 = make_float2(t0.x - t2.x, t0.y - t2.y);
    float2 E1 = make_float2(t1.x + it3.x, t1.y + it3.y);
    float2 E3 = make_float2(t1.x - it3.x, t1.y - it3.y);
    float2 O0 = make_float2(u0.x + u2.x, u0.y + u2.y);
    float2 O2 = make_float2(u0.x - u2.x, u0.y - u2.y);
    float2 O1 = make_float2(u1.x + iu3.x, u1.y + iu3.y);
    float2 O3 = make_float2(u1.x - iu3.x, u1.y - iu3.y);
    float2 w1o = make_float2(C * (O1.x - sg * O1.y), C * (O1.y + sg * O1.x));
    float2 w2o = muli<SGN>(O2);
    float2 w3o = make_float2(-C * (O3.x + sg * O3.y), C * (sg * O3.x - O3.y));
    v[0] = make_float2(E0.x + O0.x, E0.y + O0.y);
    v[4] = make_float2(E0.x - O0.x, E0.y - O0.y);
    v[1] = make_float2(E1.x + w1o.x, E1.y + w1o.y);
    v[5] = make_float2(E1.x - w1o.x, E1.y - w1o.y);
    v[2] = make_float2(E2.x + w2o.x, E2.y + w2o.y);
    v[6] = make_float2(E2.x - w2o.x, E2.y - w2o.y);
    v[3] = make_float2(E3.x + w3o.x, E3.y + w3o.y);
    v[7] = make_float2(E3.x - w3o.x, E3.y - w3o.y);
}

// v[k] *= w^{p*k}, w = e^{SGN*2*pi*i*p*invn}
template <int SGN>
__device__ __forceinline__ void twid(float2 v[8], int p, float invn) {
    float ang = (float)SGN * 6.28318530717958647692f * (float)p * invn;
    float s, c;
    __sincosf(ang, &s, &c);
    float2 w = make_float2(c, s);
    float2 tw = w;
    v[1] = cmulf(v[1], tw);
#pragma unroll
    for (int k = 2; k < 8; k++) {
        tw = cmulf(tw, w);
        v[k] = cmulf(v[k], tw);
    }
}

// 512-pt Stockham radix-8: entry v[j] = x[lane + 64*j]; exit v[k] = X[lane + 64*k].
template <int SGN>
__device__ __forceinline__ void fft512(float2 v[8], float* Ar, float* Ai,
                                       float* Br, float* Bi, int lane) {
    dft8<SGN>(v);
    twid<SGN>(v, lane, 1.0f / 512.0f);
#pragma unroll
    for (int k = 0; k < 8; k++) {
        int id = PADI(8 * lane + k);
        Br[id] = v[k].x; Bi[id] = v[k].y;
    }
    __syncthreads();
#pragma unroll
    for (int j = 0; j < 8; j++) {
        int id = PADI(lane + 64 * j);
        v[j].x = Br[id]; v[j].y = Bi[id];
    }
    dft8<SGN>(v);
    twid<SGN>(v, lane >> 3, 1.0f / 64.0f);
    {
        int q = lane & 7, p = lane >> 3;
#pragma unroll
        for (int k = 0; k < 8; k++) {
            int id = PADI(q + 64 * p + 8 * k);
            Ar[id] = v[k].x; Ai[id] = v[k].y;
        }
    }
    __syncthreads();
#pragma unroll
    for (int j = 0; j < 8; j++) {
        int id = PADI(lane + 64 * j);
        v[j].x = Ar[id]; v[j].y = Ai[id];
    }
    dft8<SGN>(v);
}

// ---------------- init kernels ----------------

__global__ void __launch_bounds__(256) k_initH() {
    int idx = blockIdx.x * 256 + threadIdx.x;
    if (idx >= NWL * HH * HH) return;
    int w = idx / (HH * HH);
    int r = (idx >> 9) & 511;
    int c = idx & 511;
    const float wls[3] = {5.32e-07f, 6.33e-07f, 8.5e-07f};
    const float TW = 6.28318530717958647692f;
    float mr = (float)((r < 256) ? r : r - 512);
    float mc = (float)((c < 256) ? c : c - 512);
    double invnd = 1.0 / (512.0 * 8e-06);
    float fr = (float)((double)mr * invnd);
    float fc = (float)((double)mc * invnd);
    float kx = __fmul_rn(TW, fr);
    float ky = __fmul_rn(TW, fc);
    float kk = __fdiv_rn(TW, wls[w]);
    float arg = __fsub_rn(__fsub_rn(__fmul_rn(kk, kk), __fmul_rn(kx, kx)),
                          __fmul_rn(ky, ky));
    const float SL = 1.0f / 512.0f;
    const float SD = 1.0f / 512.0f;   // FIX: one F_r^-1*F_r pair cancelled => 11 factors, not 12
    float2 hl, hd;
    if (arg >= 0.0f) {
        float kz = __fsqrt_rn(arg);
        float thL = __fmul_rn(kz, 0.03f);
        float thD = __fmul_rn(kz, 0.1f);
        double sl, cl, sd, cd;
        sincos((double)thL, &sl, &cl);
        sincos((double)thD, &sd, &cd);
        hl = make_float2((float)cl * SL, (float)sl * SL);
        hd = make_float2((float)cd * SD, (float)sd * SD);
    } else {  // evanescent
        float a = __fsqrt_rn(-arg);
        hl = make_float2(expf(-__fmul_rn(a, 0.03f)) * SL, 0.0f);
        hd = make_float2(expf(-__fmul_rn(a, 0.1f)) * SD, 0.0f);
    }
    d_HL[idx] = hl;  // arg symmetric in (r,c) => no transpose needed
    d_HD[idx] = hd;
}

__global__ void __launch_bounds__(256) k_initP(const float* __restrict__ pm) {
    int idx = blockIdx.x * 256 + threadIdx.x;
    if (idx >= NLAY * NWL * HH * HH) return;
    float p = pm[idx];
    float s, c;
    __sincosf(p, &s, &c);
    int layer = idx / (NWL * HH * HH);
    float sc = (layer == 0) ? 1.0f : (1.0f / 512.0f);
    d_expP[idx] = make_float2(c * sc, s * sc);
}

// ---------------- pipeline kernels (4 lines / 256 threads per block) ----------------

__global__ void __launch_bounds__(256) k_first(const float* __restrict__ xr,
                                               const float* __restrict__ xi,
                                               float2* __restrict__ f) {
    __shared__ float Ar[4 * LBUF], Ai[4 * LBUF], Br[4 * LBUF], Bi[4 * LBUF];
    int li = threadIdx.x >> 6, lane = threadIdx.x & 63;
    int line = blockIdx.x * 4 + li;
    int img = line >> 9, y = line & 511, w = img % 3;
    const float2* P = d_expP + ((size_t)w * HH + y) * HH;  // layer 0
    size_t base = (size_t)line * HH;
    float2 v[8];
#pragma unroll
    for (int j = 0; j < 8; j++) {
        int x = lane + 64 * j;
        float2 a = make_float2(xr[base + x], xi[base + x]);
        v[j] = cmulf(a, P[x]);
    }
    fft512<-1>(v, Ar + li * LBUF, Ai + li * LBUF, Br + li * LBUF, Bi + li * LBUF, lane);
#pragma unroll
    for (int k = 0; k < 8; k++) f[base + lane + 64 * k] = v[k];
}

__global__ void __launch_bounds__(256) k_rowmid(float2* __restrict__ f, int layer) {
    __shared__ float Ar[4 * LBUF], Ai[4 * LBUF], Br[4 * LBUF], Bi[4 * LBUF];
    int li = threadIdx.x >> 6, lane = threadIdx.x & 63;
    int line = blockIdx.x * 4 + li;
    int img = line >> 9, y = line & 511, w = img % 3;
    const float2* P = d_expP + (((size_t)layer * NWL + w) * HH + y) * HH;
    size_t base = (size_t)line * HH;
    float* ar = Ar + li * LBUF; float* ai = Ai + li * LBUF;
    float* br = Br + li * LBUF; float* bi = Bi + li * LBUF;
    float2 v[8];
#pragma unroll
    for (int j = 0; j < 8; j++) v[j] = f[base + lane + 64 * j];
    fft512<1>(v, ar, ai, br, bi, lane);
#pragma unroll
    for (int k = 0; k < 8; k++) v[k] = cmulf(v[k], P[lane + 64 * k]);
    fft512<-1>(v, ar, ai, br, bi, lane);
#pragma unroll
    for (int k = 0; k < 8; k++) f[base + lane + 64 * k] = v[k];
}

__global__ void __launch_bounds__(256) k_last(float2* __restrict__ f) {
    __shared__ float Ar[4 * LBUF], Ai[4 * LBUF], Br[4 * LBUF], Bi[4 * LBUF];
    int li = threadIdx.x >> 6, lane = threadIdx.x & 63;
    int line = blockIdx.x * 4 + li;
    size_t base = (size_t)line * HH;
    float2 v[8];
#pragma unroll
    for (int j = 0; j < 8; j++) v[j] = f[base + lane + 64 * j];
    fft512<1>(v, Ar + li * LBUF, Ai + li * LBUF, Br + li * LBUF, Bi + li * LBUF, lane);
    const float S = 1.0f / 512.0f;
#pragma unroll
    for (int k = 0; k < 8; k++)
        f[base + lane + 64 * k] = make_float2(v[k].x * S, v[k].y * S);
}

// col pass: fwd col FFT, * H (scales folded), inv col FFT; 4 cols / block
__global__ void __launch_bounds__(256) k_col(float2* __restrict__ f, int det) {
    __shared__ float Ar[4 * LBUF], Ai[4 * LBUF], Br[4 * LBUF], Bi[4 * LBUF];
    int img = blockIdx.x >> 7;
    int c0 = (blockIdx.x & 127) << 2;
    int col = threadIdx.x >> 6, lane = threadIdx.x & 63;
    int w = img % 3;
    float2* base = f + (size_t)img * (HH * HH);
#pragma unroll
    for (int it = 0; it < 2; it++) {
        int r = it * 256 + threadIdx.x;
        const float2* gp = base + (size_t)r * HH + c0;
#pragma unroll
        for (int cc = 0; cc < 4; cc++) {
            float2 t = gp[cc];
            int id = cc * LBUF + PADI(r);
            Ar[id] = t.x; Ai[id] = t.y;
        }
    }
    __syncthreads();
    float* ar = Ar + col * LBUF; float* ai = Ai + col * LBUF;
    float* br = Br + col * LBUF; float* bi = Bi + col * LBUF;
    float2 v[8];
#pragma unroll
    for (int j = 0; j < 8; j++) {
        int id = PADI(lane + 64 * j);
        v[j] = make_float2(ar[id], ai[id]);
    }
    fft512<-1>(v, ar, ai, br, bi, lane);
    const float2* Hc = (det ? d_HD : d_HL) + ((size_t)w * HH + (c0 + col)) * HH;
#pragma unroll
    for (int k = 0; k < 8; k++) v[k] = cmulf(v[k], Hc[lane + 64 * k]);
    fft512<1>(v, ar, ai, br, bi, lane);
#pragma unroll
    for (int k = 0; k < 8; k++) {
        int id = PADI(lane + 64 * k);
        br[id] = v[k].x; bi[id] = v[k].y;
    }
    __syncthreads();
#pragma unroll
    for (int it = 0; it < 2; it++) {
        int r = it * 256 + threadIdx.x;
        float2* gp = base + (size_t)r * HH + c0;
#pragma unroll
        for (int cc = 0; cc < 4; cc++) {
            int id = cc * LBUF + PADI(r);
            gp[cc] = make_float2(Br[id], Bi[id]);
        }
    }
}

// ---------------- launch ----------------
// Chain:  k_first | repeat l=0..4: k_col(HL), (l<4: k_rowmid(l+1)) | k_col(HD) | k_last
extern "C" void kernel_launch(void* const* d_in, const int* in_sizes, int n_in,
                              void* d_out, int out_size) {
    const float* xr = (const float*)d_in[0];
    const float* xi = (const float*)d_in[1];
    const float* pm = (const float*)d_in[2];
    float2* f = (float2*)d_out;

    k_initH<<<(NWL * HH * HH + 255) / 256, 256>>>();
    k_initP<<<(NLAY * NWL * HH * HH + 255) / 256, 256>>>(pm);

    const int ROWBLKS = NIMG * HH / 4;       // 9216
    const int COLBLKS = NIMG * (HH / 4);     // 9216

    k_first<<<ROWBLKS, 256>>>(xr, xi, f);
    for (int l = 0; l < NLAY; l++) {
        k_col<<<COLBLKS, 256>>>(f, 0);
        if (l < NLAY - 1) k_rowmid<<<ROWBLKS, 256>>>(f, l + 1);
    }
    k_col<<<COLBLKS, 256>>>(f, 1);
    k_last<<<ROWBLKS, 256>>>(f);
}

// round 4
// speedup vs baseline: 1.4584x; 1.4584x over previous
#include <cuda_runtime.h>
#include <math.h>

#define HH    512
#define NIMG  72          // B(8) * M(3) * W(3); wavelength = img % 3
#define NWL   3
#define NLAY  5
#define LBUF  576         // row-kernel padding: 512 + 512/8
#define PADI(i) ((i) + ((i) >> 3))

#define CTILE 16          // columns per k_col block
#define CSTR  577         // per-column plane stride (odd -> cross-plane bank spread; >= 575)

// -------- precomputed tables (__device__ globals = sanctioned scratch) --------
__device__ float2 d_HL[NWL * HH * HH];               // exp(i kz zL) / 512
__device__ float2 d_HD[NWL * HH * HH];               // exp(i kz zD) / 512
__device__ float2 d_expP[NLAY * NWL * HH * HH];      // exp(i phase) (layers>0 scaled 1/512)

__device__ __forceinline__ float2 cmulf(float2 a, float2 b) {
    return make_float2(a.x * b.x - a.y * b.y, a.x * b.y + a.y * b.x);
}

template <int SGN>
__device__ __forceinline__ float2 muli(float2 z) {   // SGN * i * z
    return (SGN > 0) ? make_float2(-z.y, z.x) : make_float2(z.y, -z.x);
}

// natural-order 8-point DFT: b_k = sum_j a_j * e^{SGN*2*pi*i*j*k/8}
template <int SGN>
__device__ __forceinline__ void dft8(float2 v[8]) {
    const float C = 0.70710678118654752f;
    const float sg = (float)SGN;
    float2 t0 = make_float2(v[0].x + v[4].x, v[0].y + v[4].y);
    float2 t1 = make_float2(v[0].x - v[4].x, v[0].y - v[4].y);
    float2 t2 = make_float2(v[2].x + v[6].x, v[2].y + v[6].y);
    float2 t3 = make_float2(v[2].x - v[6].x, v[2].y - v[6].y);
    float2 u0 = make_float2(v[1].x + v[5].x, v[1].y + v[5].y);
    float2 u1 = make_float2(v[1].x - v[5].x, v[1].y - v[5].y);
    float2 u2 = make_float2(v[3].x + v[7].x, v[3].y + v[7].y);
    float2 u3 = make_float2(v[3].x - v[7].x, v[3].y - v[7].y);
    float2 it3 = muli<SGN>(t3);
    float2 iu3 = muli<SGN>(u3);
    float2 E0 = make_float2(t0.x + t2.x, t0.y + t2.y);
    float2 E2 = make_float2(t0.x - t2.x, t0.y - t2.y);
    float2 E1 = make_float2(t1.x + it3.x, t1.y + it3.y);
    float2 E3 = make_float2(t1.x - it3.x, t1.y - it3.y);
    float2 O0 = make_float2(u0.x + u2.x, u0.y + u2.y);
    float2 O2 = make_float2(u0.x - u2.x, u0.y - u2.y);
    float2 O1 = make_float2(u1.x + iu3.x, u1.y + iu3.y);
    float2 O3 = make_float2(u1.x - iu3.x, u1.y - iu3.y);
    float2 w1o = make_float2(C * (O1.x - sg * O1.y), C * (O1.y + sg * O1.x));
    float2 w2o = muli<SGN>(O2);
    float2 w3o = make_float2(-C * (O3.x + sg * O3.y), C * (sg * O3.x - O3.y));
    v[0] = make_float2(E0.x + O0.x, E0.y + O0.y);
    v[4] = make_float2(E0.x - O0.x, E0.y - O0.y);
    v[1] = make_float2(E1.x + w1o.x, E1.y + w1o.y);
    v[5] = make_float2(E1.x - w1o.x, E1.y - w1o.y);
    v[2] = make_float2(E2.x + w2o.x, E2.y + w2o.y);
    v[6] = make_float2(E2.x - w2o.x, E2.y - w2o.y);
    v[3] = make_float2(E3.x + w3o.x, E3.y + w3o.y);
    v[7] = make_float2(E3.x - w3o.x, E3.y - w3o.y);
}

// v[k] *= w^{p*k}, w = e^{SGN*2*pi*i*p*invn}
template <int SGN>
__device__ __forceinline__ void twid(float2 v[8], int p, float invn) {
    float ang = (float)SGN * 6.28318530717958647692f * (float)p * invn;
    float s, c;
    __sincosf(ang, &s, &c);
    float2 w = make_float2(c, s);
    float2 tw = w;
    v[1] = cmulf(v[1], tw);
#pragma unroll
    for (int k = 2; k < 8; k++) {
        tw = cmulf(tw, w);
        v[k] = cmulf(v[k], tw);
    }
}

// ---- ping-pong version (row kernels): entry v[j]=x[lane+64j]; exit v[k]=X[lane+64k]
template <int SGN>
__device__ __forceinline__ void fft512(float2 v[8], float* Ar, float* Ai,
                                       float* Br, float* Bi, int lane) {
    dft8<SGN>(v);
    twid<SGN>(v, lane, 1.0f / 512.0f);
#pragma unroll
    for (int k = 0; k < 8; k++) {
        int id = PADI(8 * lane + k);
        Br[id] = v[k].x; Bi[id] = v[k].y;
    }
    __syncthreads();
#pragma unroll
    for (int j = 0; j < 8; j++) {
        int id = PADI(lane + 64 * j);
        v[j].x = Br[id]; v[j].y = Bi[id];
    }
    dft8<SGN>(v);
    twid<SGN>(v, lane >> 3, 1.0f / 64.0f);
    {
        int q = lane & 7, p = lane >> 3;
#pragma unroll
        for (int k = 0; k < 8; k++) {
            int id = PADI(q + 64 * p + 8 * k);
            Ar[id] = v[k].x; Ai[id] = v[k].y;
        }
    }
    __syncthreads();
#pragma unroll
    for (int j = 0; j < 8; j++) {
        int id = PADI(lane + 64 * j);
        v[j].x = Ar[id]; v[j].y = Ai[id];
    }
    dft8<SGN>(v);
}

// ---- in-place version (col kernel): single plane (tr,ti); write-set == read-set
// == {PADI(i)}, so WAR syncs make in-place safe. Caller pre-loads v from plane.
template <int SGN>
__device__ __forceinline__ void fft512_ip(float2 v[8], float* tr, float* ti, int lane) {
    dft8<SGN>(v);
    twid<SGN>(v, lane, 1.0f / 512.0f);
    __syncthreads();                       // WAR: prior plane reads complete
#pragma unroll
    for (int k = 0; k < 8; k++) {
        int id = PADI(8 * lane + k);
        tr[id] = v[k].x; ti[id] = v[k].y;
    }
    __syncthreads();
#pragma unroll
    for (int j = 0; j < 8; j++) {
        int id = PADI(lane + 64 * j);
        v[j].x = tr[id]; v[j].y = ti[id];
    }
    dft8<SGN>(v);
    twid<SGN>(v, lane >> 3, 1.0f / 64.0f);
    __syncthreads();                       // WAR
    {
        int q = lane & 7, p = lane >> 3;
#pragma unroll
        for (int k = 0; k < 8; k++) {
            int id = PADI(q + 64 * p + 8 * k);
            tr[id] = v[k].x; ti[id] = v[k].y;
        }
    }
    __syncthreads();
#pragma unroll
    for (int j = 0; j < 8; j++) {
        int id = PADI(lane + 64 * j);
        v[j].x = tr[id]; v[j].y = ti[id];
    }
    dft8<SGN>(v);
}

// ---------------- init kernels ----------------

__global__ void __launch_bounds__(256) k_initH() {
    int idx = blockIdx.x * 256 + threadIdx.x;
    if (idx >= NWL * HH * HH) return;
    int w = idx / (HH * HH);
    int r = (idx >> 9) & 511;
    int c = idx & 511;
    const float wls[3] = {5.32e-07f, 6.33e-07f, 8.5e-07f};
    const float TW = 6.28318530717958647692f;
    float mr = (float)((r < 256) ? r : r - 512);
    float mc = (float)((c < 256) ? c : c - 512);
    double invnd = 1.0 / (512.0 * 8e-06);
    float fr = (float)((double)mr * invnd);
    float fc = (float)((double)mc * invnd);
    float kx = __fmul_rn(TW, fr);
    float ky = __fmul_rn(TW, fc);
    float kk = __fdiv_rn(TW, wls[w]);
    float arg = __fsub_rn(__fsub_rn(__fmul_rn(kk, kk), __fmul_rn(kx, kx)),
                          __fmul_rn(ky, ky));
    const float SL = 1.0f / 512.0f;
    const float SD = 1.0f / 512.0f;   // 11 total 1/512 factors (one F_r pair cancelled)
    float2 hl, hd;
    if (arg >= 0.0f) {
        float kz = __fsqrt_rn(arg);
        float thL = __fmul_rn(kz, 0.03f);
        float thD = __fmul_rn(kz, 0.1f);
        double sl, cl, sd, cd;
        sincos((double)thL, &sl, &cl);
        sincos((double)thD, &sd, &cd);
        hl = make_float2((float)cl * SL, (float)sl * SL);
        hd = make_float2((float)cd * SD, (float)sd * SD);
    } else {  // evanescent
        float a = __fsqrt_rn(-arg);
        hl = make_float2(expf(-__fmul_rn(a, 0.03f)) * SL, 0.0f);
        hd = make_float2(expf(-__fmul_rn(a, 0.1f)) * SD, 0.0f);
    }
    d_HL[idx] = hl;  // arg symmetric in (r,c) => no transpose needed
    d_HD[idx] = hd;
}

__global__ void __launch_bounds__(256) k_initP(const float* __restrict__ pm) {
    int idx = blockIdx.x * 256 + threadIdx.x;
    if (idx >= NLAY * NWL * HH * HH) return;
    float p = pm[idx];
    float s, c;
    __sincosf(p, &s, &c);
    int layer = idx / (NWL * HH * HH);
    float sc = (layer == 0) ? 1.0f : (1.0f / 512.0f);
    d_expP[idx] = make_float2(c * sc, s * sc);
}

// ---------------- row-direction kernels (4 lines / 256 threads per block) ----------------

__global__ void __launch_bounds__(256) k_first(const float* __restrict__ xr,
                                               const float* __restrict__ xi,
                                               float2* __restrict__ f) {
    __shared__ float Ar[4 * LBUF], Ai[4 * LBUF], Br[4 * LBUF], Bi[4 * LBUF];
    int li = threadIdx.x >> 6, lane = threadIdx.x & 63;
    int line = blockIdx.x * 4 + li;
    int img = line >> 9, y = line & 511, w = img % 3;
    const float2* P = d_expP + ((size_t)w * HH + y) * HH;  // layer 0
    size_t base = (size_t)line * HH;
    float2 v[8];
#pragma unroll
    for (int j = 0; j < 8; j++) {
        int x = lane + 64 * j;
        float2 a = make_float2(xr[base + x], xi[base + x]);
        v[j] = cmulf(a, P[x]);
    }
    fft512<-1>(v, Ar + li * LBUF, Ai + li * LBUF, Br + li * LBUF, Bi + li * LBUF, lane);
#pragma unroll
    for (int k = 0; k < 8; k++) f[base + lane + 64 * k] = v[k];
}

__global__ void __launch_bounds__(256) k_rowmid(float2* __restrict__ f, int layer) {
    __shared__ float Ar[4 * LBUF], Ai[4 * LBUF], Br[4 * LBUF], Bi[4 * LBUF];
    int li = threadIdx.x >> 6, lane = threadIdx.x & 63;
    int line = blockIdx.x * 4 + li;
    int img = line >> 9, y = line & 511, w = img % 3;
    const float2* P = d_expP + (((size_t)layer * NWL + w) * HH + y) * HH;
    size_t base = (size_t)line * HH;
    float* ar = Ar + li * LBUF; float* ai = Ai + li * LBUF;
    float* br = Br + li * LBUF; float* bi = Bi + li * LBUF;
    float2 v[8];
#pragma unroll
    for (int j = 0; j < 8; j++) v[j] = f[base + lane + 64 * j];
    fft512<1>(v, ar, ai, br, bi, lane);
#pragma unroll
    for (int k = 0; k < 8; k++) v[k] = cmulf(v[k], P[lane + 64 * k]);
    fft512<-1>(v, ar, ai, br, bi, lane);
#pragma unroll
    for (int k = 0; k < 8; k++) f[base + lane + 64 * k] = v[k];
}

__global__ void __launch_bounds__(256) k_last(float2* __restrict__ f) {
    __shared__ float Ar[4 * LBUF], Ai[4 * LBUF], Br[4 * LBUF], Bi[4 * LBUF];
    int li = threadIdx.x >> 6, lane = threadIdx.x & 63;
    int line = blockIdx.x * 4 + li;
    size_t base = (size_t)line * HH;
    float2 v[8];
#pragma unroll
    for (int j = 0; j < 8; j++) v[j] = f[base + lane + 64 * j];
    fft512<1>(v, Ar + li * LBUF, Ai + li * LBUF, Br + li * LBUF, Bi + li * LBUF, lane);
    const float S = 1.0f / 512.0f;
#pragma unroll
    for (int k = 0; k < 8; k++)
        f[base + lane + 64 * k] = make_float2(v[k].x * S, v[k].y * S);
}

// ---------------- column pass: 16 cols x 512 rows tile, coalesced staging ----------------
// grid = NIMG * (HH/CTILE) = 72*32 ; 256 threads; dynamic smem 2*CTILE*CSTR floats (72 KB)

__global__ void __launch_bounds__(256) k_col(float2* __restrict__ f, int det) {
    extern __shared__ float sm[];
    float* Tr = sm;
    float* Ti = sm + CTILE * CSTR;
    int img = blockIdx.x >> 5;                 // HH/CTILE = 32 tiles per image
    int c0 = (blockIdx.x & 31) << 4;
    int w = img % 3;
    float2* base = f + (size_t)img * (HH * HH);

    int colL = threadIdx.x & 15;               // staging map: warp = 2 rows x 16 cols
    int rowq = threadIdx.x >> 4;
#pragma unroll 4
    for (int it = 0; it < 32; it++) {
        int r = it * 16 + rowq;
        float2 t = base[(size_t)r * HH + c0 + colL];   // 128B-contiguous per row
        int id = colL * CSTR + PADI(r);
        Tr[id] = t.x; Ti[id] = t.y;
    }
    __syncthreads();

    int lane = threadIdx.x & 63;
    int cbase = threadIdx.x >> 6;              // 0..3
    const float2* Hbase = (det ? d_HD : d_HL) + (size_t)w * HH * HH;
#pragma unroll 1
    for (int itc = 0; itc < 4; itc++) {
        int col = cbase * 4 + itc;
        float* tr = Tr + col * CSTR;
        float* ti = Ti + col * CSTR;
        float2 v[8];
#pragma unroll
        for (int j = 0; j < 8; j++) {
            int id = PADI(lane + 64 * j);
            v[j] = make_float2(tr[id], ti[id]);
        }
        fft512_ip<-1>(v, tr, ti, lane);
        const float2* Hc = Hbase + (size_t)(c0 + col) * HH;  // H symmetric: row==col
#pragma unroll
        for (int k = 0; k < 8; k++) v[k] = cmulf(v[k], Hc[lane + 64 * k]);
        fft512_ip<1>(v, tr, ti, lane);
        __syncthreads();                       // WAR vs last stage's loads
#pragma unroll
        for (int k = 0; k < 8; k++) {
            int id = PADI(lane + 64 * k);
            tr[id] = v[k].x; ti[id] = v[k].y;
        }
        __syncthreads();
    }

#pragma unroll 4
    for (int it = 0; it < 32; it++) {
        int r = it * 16 + rowq;
        int id = colL * CSTR + PADI(r);
        base[(size_t)r * HH + c0 + colL] = make_float2(Tr[id], Ti[id]);
    }
}

// ---------------- launch ----------------
// Chain:  k_first | repeat l=0..4: k_col(HL), (l<4: k_rowmid(l+1)) | k_col(HD) | k_last
extern "C" void kernel_launch(void* const* d_in, const int* in_sizes, int n_in,
                              void* d_out, int out_size) {
    const float* xr = (const float*)d_in[0];
    const float* xi = (const float*)d_in[1];
    const float* pm = (const float*)d_in[2];
    float2* f = (float2*)d_out;

    const int COLSMEM = 2 * CTILE * CSTR * (int)sizeof(float);   // 73,856 B
    cudaFuncSetAttribute(k_col, cudaFuncAttributeMaxDynamicSharedMemorySize, COLSMEM);

    k_initH<<<(NWL * HH * HH + 255) / 256, 256>>>();
    k_initP<<<(NLAY * NWL * HH * HH + 255) / 256, 256>>>(pm);

    const int ROWBLKS = NIMG * HH / 4;         // 9216
    const int COLBLKS = NIMG * (HH / CTILE);   // 2304

    k_first<<<ROWBLKS, 256>>>(xr, xi, f);
    for (int l = 0; l < NLAY; l++) {
        k_col<<<COLBLKS, 256, COLSMEM>>>(f, 0);
        if (l < NLAY - 1) k_rowmid<<<ROWBLKS, 256>>>(f, l + 1);
    }
    k_col<<<COLBLKS, 256, COLSMEM>>>(f, 1);
    k_last<<<ROWBLKS, 256>>>(f);
}

// round 5
// speedup vs baseline: 1.6707x; 1.1456x over previous
#include <cuda_runtime.h>
#include <math.h>

#define HH    512
#define NIMG  72          // B(8) * M(3) * W(3); wavelength = img % 3
#define NWL   3
#define NLAY  5
#define LBUF  576         // row-kernel float2 plane: 512 + 64 pad
#define PADI(i) ((i) + ((i) >> 3))

#define CTILE 16          // columns per k_col block
#define CSTR2 577         // float2 stride per column plane (>=575)

// -------- precomputed tables --------
__device__ float2 d_HL[NWL * HH * HH];               // exp(i kz zL) / 512
__device__ float2 d_HD[NWL * HH * HH];               // exp(i kz zD) / 512
__device__ float2 d_expP[NLAY * NWL * HH * HH];      // exp(i phase) (layers>0 scaled 1/512)

__device__ __forceinline__ float2 cmulf(float2 a, float2 b) {
    return make_float2(a.x * b.x - a.y * b.y, a.x * b.y + a.y * b.x);
}

template <int SGN>
__device__ __forceinline__ float2 muli(float2 z) {   // SGN * i * z
    return (SGN > 0) ? make_float2(-z.y, z.x) : make_float2(z.y, -z.x);
}

__device__ __forceinline__ void barg(int id) {       // named barrier, 64 threads
    asm volatile("bar.sync %0, 64;" :: "r"(id) : "memory");
}

// natural-order 8-point DFT: b_k = sum_j a_j * e^{SGN*2*pi*i*j*k/8}
template <int SGN>
__device__ __forceinline__ void dft8(float2 v[8]) {
    const float C = 0.70710678118654752f;
    const float sg = (float)SGN;
    float2 t0 = make_float2(v[0].x + v[4].x, v[0].y + v[4].y);
    float2 t1 = make_float2(v[0].x - v[4].x, v[0].y - v[4].y);
    float2 t2 = make_float2(v[2].x + v[6].x, v[2].y + v[6].y);
    float2 t3 = make_float2(v[2].x - v[6].x, v[2].y - v[6].y);
    float2 u0 = make_float2(v[1].x + v[5].x, v[1].y + v[5].y);
    float2 u1 = make_float2(v[1].x - v[5].x, v[1].y - v[5].y);
    float2 u2 = make_float2(v[3].x + v[7].x, v[3].y + v[7].y);
    float2 u3 = make_float2(v[3].x - v[7].x, v[3].y - v[7].y);
    float2 it3 = muli<SGN>(t3);
    float2 iu3 = muli<SGN>(u3);
    float2 E0 = make_float2(t0.x + t2.x, t0.y + t2.y);
    float2 E2 = make_float2(t0.x - t2.x, t0.y - t2.y);
    float2 E1 = make_float2(t1.x + it3.x, t1.y + it3.y);
    float2 E3 = make_float2(t1.x - it3.x, t1.y - it3.y);
    float2 O0 = make_float2(u0.x + u2.x, u0.y + u2.y);
    float2 O2 = make_float2(u0.x - u2.x, u0.y - u2.y);
    float2 O1 = make_float2(u1.x + iu3.x, u1.y + iu3.y);
    float2 O3 = make_float2(u1.x - iu3.x, u1.y - iu3.y);
    float2 w1o = make_float2(C * (O1.x - sg * O1.y), C * (O1.y + sg * O1.x));
    float2 w2o = muli<SGN>(O2);
    float2 w3o = make_float2(-C * (O3.x + sg * O3.y), C * (sg * O3.x - O3.y));
    v[0] = make_float2(E0.x + O0.x, E0.y + O0.y);
    v[4] = make_float2(E0.x - O0.x, E0.y - O0.y);
    v[1] = make_float2(E1.x + w1o.x, E1.y + w1o.y);
    v[5] = make_float2(E1.x - w1o.x, E1.y - w1o.y);
    v[2] = make_float2(E2.x + w2o.x, E2.y + w2o.y);
    v[6] = make_float2(E2.x - w2o.x, E2.y - w2o.y);
    v[3] = make_float2(E3.x + w3o.x, E3.y + w3o.y);
    v[7] = make_float2(E3.x - w3o.x, E3.y - w3o.y);
}

template <int SGN>
__device__ __forceinline__ void twid(float2 v[8], int p, float invn) {
    float ang = (float)SGN * 6.28318530717958647692f * (float)p * invn;
    float s, c;
    __sincosf(ang, &s, &c);
    float2 w = make_float2(c, s);
    float2 tw = w;
    v[1] = cmulf(v[1], tw);
#pragma unroll
    for (int k = 2; k < 8; k++) {
        tw = cmulf(tw, w);
        v[k] = cmulf(v[k], tw);
    }
}

// ---- row kernels: ping-pong float2 planes, block-wide sync ----
// entry v[j]=x[lane+64j]; exit v[k]=X[lane+64k]; 2 __syncthreads per FFT.
template <int SGN>
__device__ __forceinline__ void fft512_pp(float2 v[8], float2* A, float2* B, int lane) {
    dft8<SGN>(v);
    twid<SGN>(v, lane, 1.0f / 512.0f);
#pragma unroll
    for (int k = 0; k < 8; k++) B[PADI(8 * lane + k)] = v[k];
    __syncthreads();
#pragma unroll
    for (int j = 0; j < 8; j++) v[j] = B[PADI(lane + 64 * j)];
    dft8<SGN>(v);
    twid<SGN>(v, lane >> 3, 1.0f / 64.0f);
    {
        int q = lane & 7, p = lane >> 3;
#pragma unroll
        for (int k = 0; k < 8; k++) A[PADI(q + 64 * p + 8 * k)] = v[k];
    }
    __syncthreads();
#pragma unroll
    for (int j = 0; j < 8; j++) v[j] = A[PADI(lane + 64 * j)];
    dft8<SGN>(v);
}

// ---- col kernel: in-place single float2 plane, per-group named barrier ----
template <int SGN>
__device__ __forceinline__ void fft512_ip(float2 v[8], float2* t, int lane, int bid) {
    dft8<SGN>(v);
    twid<SGN>(v, lane, 1.0f / 512.0f);
    barg(bid);                              // WAR vs prior reads of t
#pragma unroll
    for (int k = 0; k < 8; k++) t[PADI(8 * lane + k)] = v[k];
    barg(bid);
#pragma unroll
    for (int j = 0; j < 8; j++) v[j] = t[PADI(lane + 64 * j)];
    dft8<SGN>(v);
    twid<SGN>(v, lane >> 3, 1.0f / 64.0f);
    barg(bid);                              // WAR
    {
        int q = lane & 7, p = lane >> 3;
#pragma unroll
        for (int k = 0; k < 8; k++) t[PADI(q + 64 * p + 8 * k)] = v[k];
    }
    barg(bid);
#pragma unroll
    for (int j = 0; j < 8; j++) v[j] = t[PADI(lane + 64 * j)];
    dft8<SGN>(v);
}

// ---------------- init kernels ----------------

__global__ void __launch_bounds__(256) k_initH() {
    int idx = blockIdx.x * 256 + threadIdx.x;
    if (idx >= NWL * HH * HH) return;
    int w = idx / (HH * HH);
    int r = (idx >> 9) & 511;
    int c = idx & 511;
    const float wls[3] = {5.32e-07f, 6.33e-07f, 8.5e-07f};
    const float TW = 6.28318530717958647692f;
    float mr = (float)((r < 256) ? r : r - 512);
    float mc = (float)((c < 256) ? c : c - 512);
    double invnd = 1.0 / (512.0 * 8e-06);
    float fr = (float)((double)mr * invnd);
    float fc = (float)((double)mc * invnd);
    float kx = __fmul_rn(TW, fr);
    float ky = __fmul_rn(TW, fc);
    float kk = __fdiv_rn(TW, wls[w]);
    float arg = __fsub_rn(__fsub_rn(__fmul_rn(kk, kk), __fmul_rn(kx, kx)),
                          __fmul_rn(ky, ky));
    const float SL = 1.0f / 512.0f;
    const float SD = 1.0f / 512.0f;   // 11 total 1/512 factors (one F_r pair cancelled)
    float2 hl, hd;
    if (arg >= 0.0f) {
        float kz = __fsqrt_rn(arg);
        float thL = __fmul_rn(kz, 0.03f);
        float thD = __fmul_rn(kz, 0.1f);
        double sl, cl, sd, cd;
        sincos((double)thL, &sl, &cl);
        sincos((double)thD, &sd, &cd);
        hl = make_float2((float)cl * SL, (float)sl * SL);
        hd = make_float2((float)cd * SD, (float)sd * SD);
    } else {  // evanescent
        float a = __fsqrt_rn(-arg);
        hl = make_float2(expf(-__fmul_rn(a, 0.03f)) * SL, 0.0f);
        hd = make_float2(expf(-__fmul_rn(a, 0.1f)) * SD, 0.0f);
    }
    d_HL[idx] = hl;  // arg symmetric in (r,c) => no transpose needed
    d_HD[idx] = hd;
}

__global__ void __launch_bounds__(256) k_initP(const float* __restrict__ pm) {
    int idx = blockIdx.x * 256 + threadIdx.x;
    if (idx >= NLAY * NWL * HH * HH) return;
    float p = pm[idx];
    float s, c;
    __sincosf(p, &s, &c);
    int layer = idx / (NWL * HH * HH);
    float sc = (layer == 0) ? 1.0f : (1.0f / 512.0f);
    d_expP[idx] = make_float2(c * sc, s * sc);
}

// ---------------- row-direction kernels (4 lines / 256 threads) ----------------

__global__ void __launch_bounds__(256) k_first(const float* __restrict__ xr,
                                               const float* __restrict__ xi,
                                               float2* __restrict__ f) {
    __shared__ float2 A[4 * LBUF], B[4 * LBUF];
    int li = threadIdx.x >> 6, lane = threadIdx.x & 63;
    int line = blockIdx.x * 4 + li;
    int img = line >> 9, y = line & 511, w = img % 3;
    const float2* P = d_expP + ((size_t)w * HH + y) * HH;  // layer 0
    size_t base = (size_t)line * HH;
    float2 v[8];
#pragma unroll
    for (int j = 0; j < 8; j++) {
        int x = lane + 64 * j;
        float2 a = make_float2(xr[base + x], xi[base + x]);
        v[j] = cmulf(a, P[x]);
    }
    fft512_pp<-1>(v, A + li * LBUF, B + li * LBUF, lane);
#pragma unroll
    for (int k = 0; k < 8; k++) f[base + lane + 64 * k] = v[k];
}

__global__ void __launch_bounds__(256) k_rowmid(float2* __restrict__ f, int layer) {
    __shared__ float2 A[4 * LBUF], B[4 * LBUF];
    int li = threadIdx.x >> 6, lane = threadIdx.x & 63;
    int line = blockIdx.x * 4 + li;
    int img = line >> 9, y = line & 511, w = img % 3;
    const float2* P = d_expP + (((size_t)layer * NWL + w) * HH + y) * HH;
    size_t base = (size_t)line * HH;
    float2* a = A + li * LBUF;
    float2* b = B + li * LBUF;
    float2 v[8];
#pragma unroll
    for (int j = 0; j < 8; j++) v[j] = f[base + lane + 64 * j];
    fft512_pp<1>(v, a, b, lane);
#pragma unroll
    for (int k = 0; k < 8; k++) v[k] = cmulf(v[k], P[lane + 64 * k]);
    // WAR across FFTs is safe: B's last read precedes the 2nd __syncthreads of
    // the previous fft512_pp; A's last read precedes the next one below.
    __syncthreads();
    fft512_pp<-1>(v, a, b, lane);
#pragma unroll
    for (int k = 0; k < 8; k++) f[base + lane + 64 * k] = v[k];
}

__global__ void __launch_bounds__(256) k_last(float2* __restrict__ f) {
    __shared__ float2 A[4 * LBUF], B[4 * LBUF];
    int li = threadIdx.x >> 6, lane = threadIdx.x & 63;
    int line = blockIdx.x * 4 + li;
    size_t base = (size_t)line * HH;
    float2 v[8];
#pragma unroll
    for (int j = 0; j < 8; j++) v[j] = f[base + lane + 64 * j];
    fft512_pp<1>(v, A + li * LBUF, B + li * LBUF, lane);
    const float S = 1.0f / 512.0f;
#pragma unroll
    for (int k = 0; k < 8; k++)
        f[base + lane + 64 * k] = make_float2(v[k].x * S, v[k].y * S);
}

// ---------------- column pass: 16 cols x 512 rows, 512 threads, 8 groups ----------------
// grid = NIMG * (HH/CTILE); dynamic smem CTILE*CSTR2 float2 (73.9 KB)

__global__ void __launch_bounds__(512, 2) k_col(float2* __restrict__ f, int det) {
    extern __shared__ float2 T[];
    int img = blockIdx.x >> 5;                 // 32 tiles per image
    int c0 = (blockIdx.x & 31) << 4;
    int w = img % 3;
    float2* base = f + (size_t)img * (HH * HH);

    int colL = threadIdx.x & 15;               // staging: warp = 2 rows x 16 cols
    int rowq = threadIdx.x >> 4;               // 0..31
#pragma unroll 4
    for (int it = 0; it < 16; it++) {
        int r = it * 32 + rowq;
        T[colL * CSTR2 + PADI(r)] = base[(size_t)r * HH + c0 + colL];
    }
    __syncthreads();

    int grp = threadIdx.x >> 6;                // 0..7
    int lane = threadIdx.x & 63;
    int bid = 1 + grp;                         // named barrier per group
    const float2* Hbase = (det ? d_HD : d_HL) + (size_t)w * HH * HH;
#pragma unroll 1
    for (int itc = 0; itc < 2; itc++) {
        int col = grp * 2 + itc;
        float2* t = T + col * CSTR2;
        float2 v[8];
#pragma unroll
        for (int j = 0; j < 8; j++) v[j] = t[PADI(lane + 64 * j)];
        fft512_ip<-1>(v, t, lane, bid);
        const float2* Hc = Hbase + (size_t)(c0 + col) * HH;  // H symmetric: row==col
#pragma unroll
        for (int k = 0; k < 8; k++) v[k] = cmulf(v[k], Hc[lane + 64 * k]);
        fft512_ip<1>(v, t, lane, bid);
        barg(bid);                             // WAR vs last stage's loads
#pragma unroll
        for (int k = 0; k < 8; k++) t[PADI(lane + 64 * k)] = v[k];
        barg(bid);
    }
    __syncthreads();

#pragma unroll 4
    for (int it = 0; it < 16; it++) {
        int r = it * 32 + rowq;
        base[(size_t)r * HH + c0 + colL] = T[colL * CSTR2 + PADI(r)];
    }
}

// ---------------- launch ----------------
// Chain: k_first | repeat l=0..4: k_col(HL), (l<4: k_rowmid(l+1)) | k_col(HD) | k_last
extern "C" void kernel_launch(void* const* d_in, const int* in_sizes, int n_in,
                              void* d_out, int out_size) {
    const float* xr = (const float*)d_in[0];
    const float* xi = (const float*)d_in[1];
    const float* pm = (const float*)d_in[2];
    float2* f = (float2*)d_out;

    const int COLSMEM = CTILE * CSTR2 * (int)sizeof(float2);   // 73,856 B
    cudaFuncSetAttribute(k_col, cudaFuncAttributeMaxDynamicSharedMemorySize, COLSMEM);

    k_initH<<<(NWL * HH * HH + 255) / 256, 256>>>();
    k_initP<<<(NLAY * NWL * HH * HH + 255) / 256, 256>>>(pm);

    const int ROWBLKS = NIMG * HH / 4;         // 9216
    const int COLBLKS = NIMG * (HH / CTILE);   // 2304

    k_first<<<ROWBLKS, 256>>>(xr, xi, f);
    for (int l = 0; l < NLAY; l++) {
        k_col<<<COLBLKS, 512, COLSMEM>>>(f, 0);
        if (l < NLAY - 1) k_rowmid<<<ROWBLKS, 256>>>(f, l + 1);
    }
    k_col<<<COLBLKS, 512, COLSMEM>>>(f, 1);
    k_last<<<ROWBLKS, 256>>>(f);
}